// round 1
// baseline (speedup 1.0000x reference)
#include <cuda_runtime.h>

#define N_NODES 50000
#define N_EDGES 1600000

// ---------------- scratch (static device globals; no runtime alloc) ----------------
__device__ float4 g_xp4[3][N_NODES * 16];    // xp[g][n][64] as float4   (38.4 MB)
__device__ float4 g_acc4[3][N_NODES * 16];   // numerator accum          (38.4 MB)
__device__ float2 g_as[3][N_NODES];          // per-node src logits (2 heads)
__device__ float2 g_ad[3][N_NODES];          // per-node dst logits
__device__ float2 g_den[3][N_NODES];         // softmax denominators
__device__ float  g_gt[3][32 * N_NODES];     // GAT outputs transposed [g][c][n]
__device__ float  g_h[32 * N_NODES];         // KAN layer-1 output transposed [o][n]

// ---------------- kernel 1: xp = x @ W_g^T for all 3 graphs ----------------
// block = 192 threads, each thread owns one (g, col) output column; 32 nodes/block.
__global__ void k_xp(const float* __restrict__ x,
                     const float* __restrict__ Wa,
                     const float* __restrict__ Wo,
                     const float* __restrict__ Wt) {
    __shared__ __align__(16) float xs[32][64];
    int o = threadIdx.x;           // 0..191
    int g = o >> 6;
    int col = o & 63;
    const float* W = (g == 0) ? Wa : (g == 1) ? Wo : Wt;
    const float4* W4 = (const float4*)(W + col * 64);
    float4 w[16];
#pragma unroll
    for (int i = 0; i < 16; i++) w[i] = W4[i];

    int nbase = blockIdx.x * 32;
    for (int idx = threadIdx.x; idx < 32 * 64; idx += 192) {
        int nn = idx >> 6, kk = idx & 63;
        int node = nbase + nn;
        xs[nn][kk] = (node < N_NODES) ? x[node * 64 + kk] : 0.f;
    }
    __syncthreads();

    float* xp = (float*)g_xp4[g];
    for (int nn = 0; nn < 32; nn++) {
        int node = nbase + nn;
        if (node >= N_NODES) break;
        const float4* xv = (const float4*)xs[nn];
        float acc = 0.f;
#pragma unroll
        for (int i = 0; i < 16; i++) {
            float4 xx = xv[i];
            acc += xx.x * w[i].x + xx.y * w[i].y + xx.z * w[i].z + xx.w * w[i].w;
        }
        xp[node * 64 + col] = acc;
    }
}

// ---------------- kernel 2: per-node attention logits ----------------
__global__ void k_att(const float* __restrict__ as0, const float* __restrict__ ad0,
                      const float* __restrict__ as1, const float* __restrict__ ad1,
                      const float* __restrict__ as2, const float* __restrict__ ad2) {
    int t = blockIdx.x * blockDim.x + threadIdx.x;
    if (t >= 3 * N_NODES) return;
    int g = t / N_NODES, n = t - g * N_NODES;
    const float4* as4 = (const float4*)((g == 0) ? as0 : (g == 1) ? as1 : as2);
    const float4* ad4 = (const float4*)((g == 0) ? ad0 : (g == 1) ? ad1 : ad2);
    const float4* xp4 = g_xp4[g] + n * 16;
    float s0 = 0, s1 = 0, d0 = 0, d1 = 0;
#pragma unroll
    for (int i = 0; i < 8; i++) {
        float4 v = xp4[i], a = as4[i], b = ad4[i];
        s0 += v.x * a.x + v.y * a.y + v.z * a.z + v.w * a.w;
        d0 += v.x * b.x + v.y * b.y + v.z * b.z + v.w * b.w;
    }
#pragma unroll
    for (int i = 8; i < 16; i++) {
        float4 v = xp4[i], a = as4[i], b = ad4[i];
        s1 += v.x * a.x + v.y * a.y + v.z * a.z + v.w * a.w;
        d1 += v.x * b.x + v.y * b.y + v.z * b.z + v.w * b.w;
    }
    g_as[g][n] = make_float2(s0, s1);
    g_ad[g][n] = make_float2(d0, d1);
}

// ---------------- kernel 3: self-loop init of accum + denom ----------------
__global__ void k_self() {
    int t = blockIdx.x * blockDim.x + threadIdx.x;
    if (t >= 3 * N_NODES) return;
    int g = t / N_NODES, n = t - g * N_NODES;
    float2 s = g_as[g][n], d = g_ad[g][n];
    float a0 = s.x + d.x; a0 = a0 > 0.f ? a0 : 0.2f * a0;
    float a1 = s.y + d.y; a1 = a1 > 0.f ? a1 : 0.2f * a1;
    float e0 = __expf(a0), e1 = __expf(a1);
    g_den[g][n] = make_float2(e0, e1);
    const float4* xp4 = g_xp4[g] + n * 16;
    float4* ac4 = g_acc4[g] + n * 16;
#pragma unroll
    for (int i = 0; i < 8; i++) {
        float4 v = xp4[i];
        ac4[i] = make_float4(v.x * e0, v.y * e0, v.z * e0, v.w * e0);
    }
#pragma unroll
    for (int i = 8; i < 16; i++) {
        float4 v = xp4[i];
        ac4[i] = make_float4(v.x * e1, v.y * e1, v.z * e1, v.w * e1);
    }
}

// ---------------- kernel 4: edge scatter pass (8 lanes / edge) ----------------
__global__ void k_edge(const int* __restrict__ e0, const int* __restrict__ e1,
                       const int* __restrict__ e2) {
    unsigned t = blockIdx.x * blockDim.x + threadIdx.x;
    unsigned eg = t >> 3;
    int sub = t & 7;
    int g = eg / N_EDGES;                 // uniform per block (50000 blocks/graph)
    int e = eg - g * N_EDGES;
    const int* ei = (g == 0) ? e0 : (g == 1) ? e1 : e2;
    int src = __ldg(ei + e);
    int dst = __ldg(ei + N_EDGES + e);
    float2 s = g_as[g][src];
    float2 d = g_ad[g][dst];
    float a0 = s.x + d.x; a0 = a0 > 0.f ? a0 : 0.2f * a0;
    float a1 = s.y + d.y; a1 = a1 > 0.f ? a1 : 0.2f * a1;
    float ex0 = __expf(a0), ex1 = __expf(a1);
    if (sub == 0) {
        float* dp = (float*)&g_den[g][dst];
        asm volatile("red.global.add.v2.f32 [%0], {%1,%2};"
                     :: "l"(dp), "f"(ex0), "f"(ex1) : "memory");
    }
    float ex = (sub < 4) ? ex0 : ex1;
    const float4* xp4 = g_xp4[g] + src * 16 + sub * 2;
    float4* ac4 = g_acc4[g] + dst * 16 + sub * 2;
    float4 v0 = xp4[0], v1 = xp4[1];
    asm volatile("red.global.add.v4.f32 [%0], {%1,%2,%3,%4};"
                 :: "l"(ac4), "f"(v0.x * ex), "f"(v0.y * ex), "f"(v0.z * ex), "f"(v0.w * ex)
                 : "memory");
    asm volatile("red.global.add.v4.f32 [%0], {%1,%2,%3,%4};"
                 :: "l"(ac4 + 1), "f"(v1.x * ex), "f"(v1.y * ex), "f"(v1.z * ex), "f"(v1.w * ex)
                 : "memory");
}

// ---------------- kernel 5: normalize, head-mean, +bias, transpose store ----------------
__global__ void k_norm(const float* __restrict__ ba, const float* __restrict__ bo,
                       const float* __restrict__ bt) {
    int t = blockIdx.x * blockDim.x + threadIdx.x;
    if (t >= 3 * N_NODES) return;
    int g = t / N_NODES, n = t - g * N_NODES;
    float2 den = g_den[g][n];
    float i0 = 0.5f / den.x, i1 = 0.5f / den.y;
    const float* b = (g == 0) ? ba : (g == 1) ? bo : bt;
    const float* ac = (const float*)(g_acc4[g]) + n * 64;
    float* gt = g_gt[g];
#pragma unroll 8
    for (int c = 0; c < 32; c++) {
        gt[c * N_NODES + n] = ac[c] * i0 + ac[32 + c] * i1 + b[c];
    }
}

// ---------------- KAN helpers ----------------
// Cox–de Boor, K=2, 8 knots, with precomputed reciprocals rA[7], rB[6]
__device__ __forceinline__ void kan_basis(float xi, const float* gr,
                                          const float* rA, const float* rB,
                                          float b2[5]) {
    float b0[7];
#pragma unroll
    for (int j = 0; j < 7; j++)
        b0[j] = (xi >= gr[j] && xi < gr[j + 1]) ? 1.f : 0.f;
    float b1[6];
#pragma unroll
    for (int j = 0; j < 6; j++)
        b1[j] = (xi - gr[j]) * rA[j] * b0[j] + (gr[j + 2] - xi) * rA[j + 1] * b0[j + 1];
#pragma unroll
    for (int j = 0; j < 5; j++)
        b2[j] = (xi - gr[j]) * rB[j] * b1[j] + (gr[j + 3] - xi) * rB[j + 1] * b1[j + 1];
}

// ---------------- kernel 6: KAN layer 1 (99 -> 32) ----------------
#define KAN1_SMEM ((3168 + 15840 + 792 + 693 + 594) * 4)
__global__ void k_kan1(const float* __restrict__ bw, const float* __restrict__ sw,
                       const float* __restrict__ grid,
                       const float* __restrict__ a0p, const float* __restrict__ a1p,
                       const float* __restrict__ a2p) {
    extern __shared__ float sm[];
    float* s_bw = sm;                 // 32*99
    float* s_sw = s_bw + 3168;        // 32*99*5
    float* s_gr = s_sw + 15840;       // 99*8
    float* s_rA = s_gr + 792;         // 99*7
    float* s_rB = s_rA + 693;         // 99*6
    for (int i = threadIdx.x; i < 3168; i += blockDim.x) s_bw[i] = bw[i];
    for (int i = threadIdx.x; i < 15840; i += blockDim.x) s_sw[i] = sw[i];
    for (int i = threadIdx.x; i < 792; i += blockDim.x) s_gr[i] = grid[i];
    for (int i = threadIdx.x; i < 99; i += blockDim.x) {
        const float* gr = grid + i * 8;
#pragma unroll
        for (int j = 0; j < 7; j++) s_rA[i * 7 + j] = 1.f / (gr[j + 1] - gr[j]);
#pragma unroll
        for (int j = 0; j < 6; j++) s_rB[i * 6 + j] = 1.f / (gr[j + 2] - gr[j]);
    }
    __syncthreads();

    int n = blockIdx.x * blockDim.x + threadIdx.x;
    if (n >= N_NODES) return;

    float aa0 = *a0p, aa1 = *a1p, aa2 = *a2p;
    float m = fmaxf(aa0, fmaxf(aa1, aa2));
    float w0 = __expf(aa0 - m), w1 = __expf(aa1 - m), w2 = __expf(aa2 - m);
    float wsum = w0 + w1 + w2;
    w0 /= wsum; w1 /= wsum; w2 /= wsum;

    float acc[32];
#pragma unroll
    for (int o = 0; o < 32; o++) acc[o] = 0.f;

    for (int i = 0; i < 99; i++) {
        float xi;
        if (i < 96) {
            int g = i >> 5, c = i & 31;
            xi = g_gt[g][c * N_NODES + n];
        } else {
            xi = (i == 96) ? w0 : (i == 97) ? w1 : w2;
        }
        float sl = xi / (1.f + __expf(-xi));
        float b2[5];
        kan_basis(xi, s_gr + i * 8, s_rA + i * 7, s_rB + i * 6, b2);
#pragma unroll
        for (int o = 0; o < 32; o++) {
            const float* swo = s_sw + (o * 99 + i) * 5;
            float tt = sl * s_bw[o * 99 + i];
            tt += b2[0] * swo[0] + b2[1] * swo[1] + b2[2] * swo[2]
                + b2[3] * swo[3] + b2[4] * swo[4];
            acc[o] += tt;
        }
    }
#pragma unroll
    for (int o = 0; o < 32; o++) g_h[o * N_NODES + n] = acc[o];
}

// ---------------- kernel 7: KAN layer 2 (32 -> 32) + relu ----------------
__global__ void k_kan2(const float* __restrict__ bw, const float* __restrict__ sw,
                       const float* __restrict__ grid, float* __restrict__ out) {
    __shared__ float s_bw[1024];     // 32*32
    __shared__ float s_sw[5120];     // 32*32*5
    __shared__ float s_gr[256];      // 32*8
    __shared__ float s_rA[224];      // 32*7
    __shared__ float s_rB[192];      // 32*6
    for (int i = threadIdx.x; i < 1024; i += blockDim.x) s_bw[i] = bw[i];
    for (int i = threadIdx.x; i < 5120; i += blockDim.x) s_sw[i] = sw[i];
    for (int i = threadIdx.x; i < 256; i += blockDim.x) s_gr[i] = grid[i];
    for (int i = threadIdx.x; i < 32; i += blockDim.x) {
        const float* gr = grid + i * 8;
#pragma unroll
        for (int j = 0; j < 7; j++) s_rA[i * 7 + j] = 1.f / (gr[j + 1] - gr[j]);
#pragma unroll
        for (int j = 0; j < 6; j++) s_rB[i * 6 + j] = 1.f / (gr[j + 2] - gr[j]);
    }
    __syncthreads();

    int n = blockIdx.x * blockDim.x + threadIdx.x;
    if (n >= N_NODES) return;

    float acc[32];
#pragma unroll
    for (int o = 0; o < 32; o++) acc[o] = 0.f;

    for (int i = 0; i < 32; i++) {
        float xi = g_h[i * N_NODES + n];
        float sl = xi / (1.f + __expf(-xi));
        float b2[5];
        kan_basis(xi, s_gr + i * 8, s_rA + i * 7, s_rB + i * 6, b2);
#pragma unroll
        for (int o = 0; o < 32; o++) {
            const float* swo = s_sw + (o * 32 + i) * 5;
            float tt = sl * s_bw[o * 32 + i];
            tt += b2[0] * swo[0] + b2[1] * swo[1] + b2[2] * swo[2]
                + b2[3] * swo[3] + b2[4] * swo[4];
            acc[o] += tt;
        }
    }
    float4* o4 = (float4*)(out + n * 32);
#pragma unroll
    for (int q = 0; q < 8; q++) {
        o4[q] = make_float4(fmaxf(acc[q * 4 + 0], 0.f), fmaxf(acc[q * 4 + 1], 0.f),
                            fmaxf(acc[q * 4 + 2], 0.f), fmaxf(acc[q * 4 + 3], 0.f));
    }
}

// ---------------- launch ----------------
extern "C" void kernel_launch(void* const* d_in, const int* in_sizes, int n_in,
                              void* d_out, int out_size) {
    const float* x    = (const float*)d_in[0];
    const int* ei0    = (const int*)d_in[1];
    const int* ei1    = (const int*)d_in[2];
    const int* ei2    = (const int*)d_in[3];
    const float* al0  = (const float*)d_in[4];
    const float* al1  = (const float*)d_in[5];
    const float* al2  = (const float*)d_in[6];
    const float* Wa   = (const float*)d_in[7];
    const float* asa  = (const float*)d_in[8];
    const float* ada  = (const float*)d_in[9];
    const float* ba   = (const float*)d_in[10];
    const float* Wo   = (const float*)d_in[11];
    const float* aso  = (const float*)d_in[12];
    const float* ado  = (const float*)d_in[13];
    const float* bo   = (const float*)d_in[14];
    const float* Wt   = (const float*)d_in[15];
    const float* ast  = (const float*)d_in[16];
    const float* adt  = (const float*)d_in[17];
    const float* bt   = (const float*)d_in[18];
    const float* bw1  = (const float*)d_in[19];
    const float* sw1  = (const float*)d_in[20];
    const float* g1   = (const float*)d_in[21];
    const float* bw2  = (const float*)d_in[22];
    const float* sw2  = (const float*)d_in[23];
    const float* g2   = (const float*)d_in[24];

    k_xp<<<(N_NODES + 31) / 32, 192>>>(x, Wa, Wo, Wt);
    k_att<<<(3 * N_NODES + 255) / 256, 256>>>(asa, ada, aso, ado, ast, adt);
    k_self<<<(3 * N_NODES + 255) / 256, 256>>>();
    k_edge<<<(3 * N_EDGES * 8) / 256, 256>>>(ei0, ei1, ei2);
    k_norm<<<(3 * N_NODES + 255) / 256, 256>>>(ba, bo, bt);
    cudaFuncSetAttribute(k_kan1, cudaFuncAttributeMaxDynamicSharedMemorySize, KAN1_SMEM);
    k_kan1<<<(N_NODES + 255) / 256, 256, KAN1_SMEM>>>(bw1, sw1, g1, al0, al1, al2);
    k_kan2<<<(N_NODES + 255) / 256, 256>>>(bw2, sw2, g2, (float*)d_out);
}

// round 2
// speedup vs baseline: 1.2278x; 1.2278x over previous
#include <cuda_runtime.h>

#define N_NODES 50000
#define N_EDGES 1600000
#define NTOT    (3 * N_NODES)
#define ETOT    (3 * N_EDGES)
#define BLKS_PER_G 1563          // ceil(50000/32)
#define FULLM 0xffffffffu

// ---------------- scratch ----------------
__device__ float4 g_xp4[3][N_NODES * 16];    // xp[g][n][64]
__device__ float  g_as[3][N_NODES * 2];      // src logits [n][head]
__device__ float  g_ad[3][N_NODES * 2];      // dst logits
__device__ int    g_deg[NTOT];
__device__ int    g_scan[NTOT];
__device__ int    g_bsum[256];
__device__ int    g_off[NTOT + 1];
__device__ int    g_cur[NTOT];
__device__ int    g_srcs[ETOT];
__device__ float  g_gt[3][32 * N_NODES];     // GAT outputs transposed [g][c][n]
__device__ float  g_h[32 * N_NODES];         // KAN1 output transposed [o][n]

// ---------------- kernel 0: zero degree counters ----------------
__global__ void k_zero() {
    int t = blockIdx.x * blockDim.x + threadIdx.x;
    if (t < NTOT) g_deg[t] = 0;
}

// ---------------- kernel 1: xp = x @ W^T (+ fused attention logits) ----------------
// 192 threads = 6 warps; warp w -> (graph g=w/2, head h=w%2); lane -> channel.
__global__ void k_xp(const float* __restrict__ x,
                     const float* __restrict__ Wa, const float* __restrict__ Wo,
                     const float* __restrict__ Wt,
                     const float* __restrict__ asa, const float* __restrict__ ada,
                     const float* __restrict__ aso, const float* __restrict__ ado,
                     const float* __restrict__ ast, const float* __restrict__ adt) {
    __shared__ __align__(16) float xs[32][64];
    int t = threadIdx.x;
    int w = t >> 5, lane = t & 31;
    int g = w >> 1, h = w & 1;
    int col = h * 32 + lane;
    const float* W = (g == 0) ? Wa : (g == 1) ? Wo : Wt;
    const float4* W4 = (const float4*)(W + col * 64);
    float4 wv[16];
#pragma unroll
    for (int i = 0; i < 16; i++) wv[i] = W4[i];
    const float* asp = (g == 0) ? asa : (g == 1) ? aso : ast;
    const float* adp = (g == 0) ? ada : (g == 1) ? ado : adt;
    float aw = asp[col], dw = adp[col];

    int nbase = blockIdx.x * 32;
    float4* xs4 = (float4*)xs;
    const float4* x4 = (const float4*)x;
    for (int idx = t; idx < 512; idx += 192) {
        int node = nbase + (idx >> 4);
        xs4[idx] = (node < N_NODES) ? x4[(size_t)nbase * 16 + idx]
                                    : make_float4(0.f, 0.f, 0.f, 0.f);
    }
    __syncthreads();

    float* xpout = (float*)g_xp4[g];
    for (int nn = 0; nn < 32; nn++) {
        int node = nbase + nn;
        if (node >= N_NODES) break;
        const float4* xv = (const float4*)xs[nn];
        float acc = 0.f;
#pragma unroll
        for (int i = 0; i < 16; i++) {
            float4 xx = xv[i];
            acc += xx.x * wv[i].x + xx.y * wv[i].y + xx.z * wv[i].z + xx.w * wv[i].w;
        }
        xpout[node * 64 + col] = acc;
        float ps = acc * aw, pd = acc * dw;
#pragma unroll
        for (int o = 16; o; o >>= 1) {
            ps += __shfl_xor_sync(FULLM, ps, o);
            pd += __shfl_xor_sync(FULLM, pd, o);
        }
        if (lane == 0) {
            g_as[g][node * 2 + h] = ps;
            g_ad[g][node * 2 + h] = pd;
        }
    }
}

// ---------------- kernel 2: histogram of dst ----------------
__global__ void k_hist(const int* __restrict__ e0, const int* __restrict__ e1,
                       const int* __restrict__ e2) {
    int t = blockIdx.x * blockDim.x + threadIdx.x;
    if (t >= ETOT) return;
    int g = t / N_EDGES, e = t - g * N_EDGES;
    const int* ei = (g == 0) ? e0 : (g == 1) ? e1 : e2;
    int dst = __ldg(ei + N_EDGES + e);
    atomicAdd(&g_deg[g * N_NODES + dst], 1);
}

// ---------------- scan (3 kernels) ----------------
__global__ void k_scan1() {
    __shared__ int sm[1024];
    int gi = blockIdx.x * 1024 + threadIdx.x;
    int v = (gi < NTOT) ? g_deg[gi] : 0;
    sm[threadIdx.x] = v;
    __syncthreads();
#pragma unroll
    for (int off = 1; off < 1024; off <<= 1) {
        int tv = (threadIdx.x >= off) ? sm[threadIdx.x - off] : 0;
        __syncthreads();
        sm[threadIdx.x] += tv;
        __syncthreads();
    }
    if (gi < NTOT) g_scan[gi] = sm[threadIdx.x];
    if (threadIdx.x == 1023) g_bsum[blockIdx.x] = sm[1023];
}
__global__ void k_scan2(int nblk) {
    __shared__ int sm[256];
    int v = (threadIdx.x < nblk) ? g_bsum[threadIdx.x] : 0;
    sm[threadIdx.x] = v;
    __syncthreads();
#pragma unroll
    for (int off = 1; off < 256; off <<= 1) {
        int tv = (threadIdx.x >= off) ? sm[threadIdx.x - off] : 0;
        __syncthreads();
        sm[threadIdx.x] += tv;
        __syncthreads();
    }
    if (threadIdx.x < nblk) g_bsum[threadIdx.x] = sm[threadIdx.x] - v;  // exclusive
}
__global__ void k_scan3() {
    int gi = blockIdx.x * blockDim.x + threadIdx.x;
    if (gi < NTOT) {
        int inc = g_scan[gi] + g_bsum[gi >> 10];
        g_off[gi + 1] = inc;
        g_cur[gi] = inc - g_deg[gi];
    }
    if (gi == 0) g_off[0] = 0;
}

// ---------------- kernel 3: scatter src indices into CSR bins ----------------
__global__ void k_scat(const int* __restrict__ e0, const int* __restrict__ e1,
                       const int* __restrict__ e2) {
    int t = blockIdx.x * blockDim.x + threadIdx.x;
    if (t >= ETOT) return;
    int g = t / N_EDGES, e = t - g * N_EDGES;
    const int* ei = (g == 0) ? e0 : (g == 1) ? e1 : e2;
    int src = __ldg(ei + e);
    int dst = __ldg(ei + N_EDGES + e);
    int pos = atomicAdd(&g_cur[g * N_NODES + dst], 1);
    g_srcs[pos] = src;
}

// ---------------- kernel 4: per-dst gather + softmax + mean + bias + transposed store ----------
// block 256 = 8 warps; warp owns 4 dsts; block covers 32 consecutive dsts of one graph.
__global__ void k_gather(const float* __restrict__ ba, const float* __restrict__ bo,
                         const float* __restrict__ bt) {
    __shared__ float val[32][33];
    int b = blockIdx.x;
    int g = b / BLKS_PER_G;
    int nbase = (b - g * BLKS_PER_G) * 32;
    int warp = threadIdx.x >> 5, lane = threadIdx.x & 31;
    const float* xp = (const float*)g_xp4[g];
    const float* asg = g_as[g];
    const float* bias = (g == 0) ? ba : (g == 1) ? bo : bt;

    for (int k = 0; k < 4; k++) {
        int nn = warp * 4 + k;
        int n = nbase + nn;
        float o = 0.f;
        if (n < N_NODES) {
            float ad0 = g_ad[g][n * 2], ad1 = g_ad[g][n * 2 + 1];
            float s0 = asg[n * 2], s1 = asg[n * 2 + 1];
            float a0 = s0 + ad0; a0 = a0 > 0.f ? a0 : 0.2f * a0;
            float a1 = s1 + ad1; a1 = a1 > 0.f ? a1 : 0.2f * a1;
            float es0 = __expf(a0), es1 = __expf(a1);
            // self-loop contribution
            float acc0 = es0 * xp[n * 64 + lane];
            float acc1 = es1 * xp[n * 64 + 32 + lane];
            float dl0 = 0.f, dl1 = 0.f;
            int f = g * N_NODES + n;
            int beg = g_off[f], end = g_off[f + 1];
            for (int base = beg; base < end; base += 32) {
                int src = 0; float ex0 = 0.f, ex1 = 0.f;
                if (base + lane < end) {
                    src = g_srcs[base + lane];
                    float t0 = asg[src * 2] + ad0; t0 = t0 > 0.f ? t0 : 0.2f * t0;
                    float t1 = asg[src * 2 + 1] + ad1; t1 = t1 > 0.f ? t1 : 0.2f * t1;
                    ex0 = __expf(t0); ex1 = __expf(t1);
                }
                dl0 += ex0; dl1 += ex1;
                int cnt = min(32, end - base);
                for (int j = 0; j < cnt; j++) {
                    int sj = __shfl_sync(FULLM, src, j);
                    float f0 = __shfl_sync(FULLM, ex0, j);
                    float f1 = __shfl_sync(FULLM, ex1, j);
                    const float* p = xp + sj * 64;
                    acc0 += f0 * p[lane];
                    acc1 += f1 * p[lane + 32];
                }
            }
#pragma unroll
            for (int oo = 16; oo; oo >>= 1) {
                dl0 += __shfl_xor_sync(FULLM, dl0, oo);
                dl1 += __shfl_xor_sync(FULLM, dl1, oo);
            }
            float den0 = dl0 + es0, den1 = dl1 + es1;
            o = 0.5f * (acc0 / den0 + acc1 / den1) + bias[lane];
        }
        val[nn][lane] = o;
    }
    __syncthreads();
    float* gt = g_gt[g];
#pragma unroll
    for (int r = 0; r < 4; r++) {
        int idx = threadIdx.x + 256 * r;
        int c = idx >> 5, nn = idx & 31;
        int n = nbase + nn;
        if (n < N_NODES) gt[c * N_NODES + n] = val[nn][c];
    }
}

// ---------------- KAN basis: Cox–de Boor K=2, 8 knots ----------------
__device__ __forceinline__ void kan_basis(float xi, const float* gr,
                                          const float* rA, const float* rB,
                                          float b2[5]) {
    float b0[7];
#pragma unroll
    for (int j = 0; j < 7; j++)
        b0[j] = (xi >= gr[j] && xi < gr[j + 1]) ? 1.f : 0.f;
    float b1[6];
#pragma unroll
    for (int j = 0; j < 6; j++)
        b1[j] = (xi - gr[j]) * rA[j] * b0[j] + (gr[j + 2] - xi) * rA[j + 1] * b0[j + 1];
#pragma unroll
    for (int j = 0; j < 5; j++)
        b2[j] = (xi - gr[j]) * rB[j] * b1[j] + (gr[j + 3] - xi) * rB[j + 1] * b1[j + 1];
}

// ---------------- kernel 5: KAN layer 1 (99 -> 32) ----------------
#define KAN1_SMEM ((3168 + 15840 + 792 + 693 + 594) * 4)
__global__ void k_kan1(const float* __restrict__ bw, const float* __restrict__ sw,
                       const float* __restrict__ grid,
                       const float* __restrict__ a0p, const float* __restrict__ a1p,
                       const float* __restrict__ a2p) {
    extern __shared__ float sm[];
    float* s_bw = sm;
    float* s_sw = s_bw + 3168;
    float* s_gr = s_sw + 15840;
    float* s_rA = s_gr + 792;
    float* s_rB = s_rA + 693;
    for (int i = threadIdx.x; i < 3168; i += blockDim.x) s_bw[i] = bw[i];
    for (int i = threadIdx.x; i < 15840; i += blockDim.x) s_sw[i] = sw[i];
    for (int i = threadIdx.x; i < 792; i += blockDim.x) s_gr[i] = grid[i];
    for (int i = threadIdx.x; i < 99; i += blockDim.x) {
        const float* gr = grid + i * 8;
#pragma unroll
        for (int j = 0; j < 7; j++) s_rA[i * 7 + j] = 1.f / (gr[j + 1] - gr[j]);
#pragma unroll
        for (int j = 0; j < 6; j++) s_rB[i * 6 + j] = 1.f / (gr[j + 2] - gr[j]);
    }
    __syncthreads();

    int n = blockIdx.x * blockDim.x + threadIdx.x;
    if (n >= N_NODES) return;

    float aa0 = *a0p, aa1 = *a1p, aa2 = *a2p;
    float m = fmaxf(aa0, fmaxf(aa1, aa2));
    float w0 = __expf(aa0 - m), w1 = __expf(aa1 - m), w2 = __expf(aa2 - m);
    float wsum = w0 + w1 + w2;
    w0 /= wsum; w1 /= wsum; w2 /= wsum;

    float acc[32];
#pragma unroll
    for (int o = 0; o < 32; o++) acc[o] = 0.f;

    for (int i = 0; i < 99; i++) {
        float xi;
        if (i < 96) {
            int g = i >> 5, c = i & 31;
            xi = g_gt[g][c * N_NODES + n];
        } else {
            xi = (i == 96) ? w0 : (i == 97) ? w1 : w2;
        }
        float sl = xi / (1.f + __expf(-xi));
        float b2[5];
        kan_basis(xi, s_gr + i * 8, s_rA + i * 7, s_rB + i * 6, b2);
#pragma unroll
        for (int o = 0; o < 32; o++) {
            const float* swo = s_sw + (o * 99 + i) * 5;
            float tt = sl * s_bw[o * 99 + i];
            tt += b2[0] * swo[0] + b2[1] * swo[1] + b2[2] * swo[2]
                + b2[3] * swo[3] + b2[4] * swo[4];
            acc[o] += tt;
        }
    }
#pragma unroll
    for (int o = 0; o < 32; o++) g_h[o * N_NODES + n] = acc[o];
}

// ---------------- kernel 6: KAN layer 2 (32 -> 32) + relu ----------------
__global__ void k_kan2(const float* __restrict__ bw, const float* __restrict__ sw,
                       const float* __restrict__ grid, float* __restrict__ out) {
    __shared__ float s_bw[1024];
    __shared__ float s_sw[5120];
    __shared__ float s_gr[256];
    __shared__ float s_rA[224];
    __shared__ float s_rB[192];
    for (int i = threadIdx.x; i < 1024; i += blockDim.x) s_bw[i] = bw[i];
    for (int i = threadIdx.x; i < 5120; i += blockDim.x) s_sw[i] = sw[i];
    for (int i = threadIdx.x; i < 256; i += blockDim.x) s_gr[i] = grid[i];
    for (int i = threadIdx.x; i < 32; i += blockDim.x) {
        const float* gr = grid + i * 8;
#pragma unroll
        for (int j = 0; j < 7; j++) s_rA[i * 7 + j] = 1.f / (gr[j + 1] - gr[j]);
#pragma unroll
        for (int j = 0; j < 6; j++) s_rB[i * 6 + j] = 1.f / (gr[j + 2] - gr[j]);
    }
    __syncthreads();

    int n = blockIdx.x * blockDim.x + threadIdx.x;
    if (n >= N_NODES) return;

    float acc[32];
#pragma unroll
    for (int o = 0; o < 32; o++) acc[o] = 0.f;

    for (int i = 0; i < 32; i++) {
        float xi = g_h[i * N_NODES + n];
        float sl = xi / (1.f + __expf(-xi));
        float b2[5];
        kan_basis(xi, s_gr + i * 8, s_rA + i * 7, s_rB + i * 6, b2);
#pragma unroll
        for (int o = 0; o < 32; o++) {
            const float* swo = s_sw + (o * 32 + i) * 5;
            float tt = sl * s_bw[o * 32 + i];
            tt += b2[0] * swo[0] + b2[1] * swo[1] + b2[2] * swo[2]
                + b2[3] * swo[3] + b2[4] * swo[4];
            acc[o] += tt;
        }
    }
    float4* o4 = (float4*)(out + n * 32);
#pragma unroll
    for (int q = 0; q < 8; q++) {
        o4[q] = make_float4(fmaxf(acc[q * 4 + 0], 0.f), fmaxf(acc[q * 4 + 1], 0.f),
                            fmaxf(acc[q * 4 + 2], 0.f), fmaxf(acc[q * 4 + 3], 0.f));
    }
}

// ---------------- launch ----------------
extern "C" void kernel_launch(void* const* d_in, const int* in_sizes, int n_in,
                              void* d_out, int out_size) {
    const float* x    = (const float*)d_in[0];
    const int* ei0    = (const int*)d_in[1];
    const int* ei1    = (const int*)d_in[2];
    const int* ei2    = (const int*)d_in[3];
    const float* al0  = (const float*)d_in[4];
    const float* al1  = (const float*)d_in[5];
    const float* al2  = (const float*)d_in[6];
    const float* Wa   = (const float*)d_in[7];
    const float* asa  = (const float*)d_in[8];
    const float* ada  = (const float*)d_in[9];
    const float* ba   = (const float*)d_in[10];
    const float* Wo   = (const float*)d_in[11];
    const float* aso  = (const float*)d_in[12];
    const float* ado  = (const float*)d_in[13];
    const float* bo   = (const float*)d_in[14];
    const float* Wt   = (const float*)d_in[15];
    const float* ast  = (const float*)d_in[16];
    const float* adt  = (const float*)d_in[17];
    const float* bt   = (const float*)d_in[18];
    const float* bw1  = (const float*)d_in[19];
    const float* sw1  = (const float*)d_in[20];
    const float* g1   = (const float*)d_in[21];
    const float* bw2  = (const float*)d_in[22];
    const float* sw2  = (const float*)d_in[23];
    const float* g2   = (const float*)d_in[24];

    int nscan1 = (NTOT + 1023) / 1024;                 // 147
    k_zero<<<(NTOT + 255) / 256, 256>>>();
    k_xp<<<BLKS_PER_G, 192>>>(x, Wa, Wo, Wt, asa, ada, aso, ado, ast, adt);
    k_hist<<<(ETOT + 255) / 256, 256>>>(ei0, ei1, ei2);
    k_scan1<<<nscan1, 1024>>>();
    k_scan2<<<1, 256>>>(nscan1);
    k_scan3<<<(NTOT + 255) / 256, 256>>>();
    k_scat<<<(ETOT + 255) / 256, 256>>>(ei0, ei1, ei2);
    k_gather<<<3 * BLKS_PER_G, 256>>>(ba, bo, bt);
    cudaFuncSetAttribute(k_kan1, cudaFuncAttributeMaxDynamicSharedMemorySize, KAN1_SMEM);
    k_kan1<<<(N_NODES + 255) / 256, 256, KAN1_SMEM>>>(bw1, sw1, g1, al0, al1, al2);
    k_kan2<<<(N_NODES + 255) / 256, 256>>>(bw2, sw2, g2, (float*)d_out);
}